// round 12
// baseline (speedup 1.0000x reference)
#include <cuda_runtime.h>
#include <cuda_fp16.h>
#include <cstdint>

#define Bz 128
#define Sz 1024
#define Dz 64
#define Hz 128
#define Oz 512
#define Mz (Bz*Sz)   /* 131072 */
#define Kz 1024
#define PI_F 3.14159265358979f
#define TWO_PI_F 6.28318530717959f

// ---- static device scratch ----
__device__ float g_pt [(size_t)Mz*Hz];                  // encoder output, PRE-WRAPPED
__device__ __align__(16) __half g_Bp [(size_t)Oz*Kz];   // 8-slot weights (slow path)
__device__ __align__(16) __half g_Bp4[(size_t)Oz*512];  // 4-slot weights (fast path) [n][h*4+jf]
__device__ __align__(16) float  g_B6 [Hz*Oz];           // w6 (ph) fp32 [h][n]
__device__ float g_W45[2*Oz];                           // column sums of w4, w5
__device__ int   g_rep[Sz];
__device__ int   g_anyrep;

// ============================ helpers ============================
__device__ __forceinline__ uint32_t h2_to_u32(__half2 v){
    return *reinterpret_cast<uint32_t*>(&v);
}
__device__ __forceinline__ uint32_t smem_u32(const void* p){
    uint32_t a;
    asm("{ .reg .u64 t; cvta.to.shared.u64 t, %1; cvt.u32.u64 %0, t; }" : "=r"(a) : "l"(p));
    return a;
}
__device__ __forceinline__ uint32_t swz(uint32_t b){ return b ^ ((b >> 3) & 0x70); }

__device__ __forceinline__ void ldsm_x4(uint32_t* r, uint32_t addr){
    asm volatile("ldmatrix.sync.aligned.m8n8.x4.shared.b16 {%0,%1,%2,%3}, [%4];"
        : "=r"(r[0]), "=r"(r[1]), "=r"(r[2]), "=r"(r[3]) : "r"(addr));
}
__device__ __forceinline__ void mma16816(float* d, const uint32_t* a, const uint32_t* b){
    asm volatile("mma.sync.aligned.m16n8k16.row.col.f32.f16.f16.f32 "
        "{%0,%1,%2,%3}, {%4,%5,%6,%7}, {%8,%9}, {%0,%1,%2,%3};"
        : "+f"(d[0]), "+f"(d[1]), "+f"(d[2]), "+f"(d[3])
        : "r"(a[0]), "r"(a[1]), "r"(a[2]), "r"(a[3]), "r"(b[0]), "r"(b[1]));
}
__device__ __forceinline__ void cp_async16(uint32_t dst, const void* src){
    asm volatile("cp.async.cg.shared.global [%0], [%1], 16;" :: "r"(dst), "l"(src));
}
#define CP_COMMIT() asm volatile("cp.async.commit_group;" ::: "memory")
#define CP_WAIT0()  asm volatile("cp.async.wait_group 0;" ::: "memory")

__device__ __forceinline__ void ffma2(float2* d, float2 a, float2 b){
    unsigned long long ua = *reinterpret_cast<unsigned long long*>(&a);
    unsigned long long ub = *reinterpret_cast<unsigned long long*>(&b);
    unsigned long long ud = *reinterpret_cast<unsigned long long*>(d);
    asm("fma.rn.f32x2 %0, %1, %2, %0;" : "+l"(ud) : "l"(ua), "l"(ub));
    *d = *reinterpret_cast<float2*>(&ud);
}

// ---- fast sin/sincos with magic-number range reduction ----
__device__ __forceinline__ float wrap_pi(float x){
    float k = fmaf(x, 0.15915494309189535f, 12582912.0f);
    k -= 12582912.0f;
    float r = fmaf(k, -6.28125f, x);
    r = fmaf(k, -1.9353071795864769e-3f, r);
    return r;
}
__device__ __forceinline__ float fsin(float x){ return __sinf(wrap_pi(x)); }
__device__ __forceinline__ void fsincos(float x, float* s, float* c){ __sincosf(wrap_pi(x), s, c); }

// ============================ 1) encoder (stores wrapped pt) ============================
__global__ __launch_bounds__(256) void encoder_kernel(const float* __restrict__ x,
                                                      const float* __restrict__ We,
                                                      const float* __restrict__ be){
    __shared__ __align__(16) float WeT[Dz*Hz];
    __shared__ float xs[32*Dz];
    int t = threadIdx.x;
    int m0 = blockIdx.x * 32;
    for (int i = t; i < Dz*Hz; i += 256){ int h = i >> 6, k = i & 63; WeT[k*Hz + h] = We[i]; }
    for (int i = t; i < 32*Dz; i += 256) xs[i] = x[(size_t)m0*Dz + i];
    __syncthreads();
    int r = t >> 3, hg = t & 7;
    float acc[16];
    #pragma unroll
    for (int j = 0; j < 16; j++) acc[j] = 0.f;
    #pragma unroll 4
    for (int k = 0; k < Dz; k++){
        float xv = xs[r*Dz + k];
        const float4* wp = (const float4*)&WeT[k*Hz + hg*16];
        float4 w0 = wp[0], w1 = wp[1], w2 = wp[2], w3 = wp[3];
        acc[0]=fmaf(xv,w0.x,acc[0]);   acc[1]=fmaf(xv,w0.y,acc[1]);
        acc[2]=fmaf(xv,w0.z,acc[2]);   acc[3]=fmaf(xv,w0.w,acc[3]);
        acc[4]=fmaf(xv,w1.x,acc[4]);   acc[5]=fmaf(xv,w1.y,acc[5]);
        acc[6]=fmaf(xv,w1.z,acc[6]);   acc[7]=fmaf(xv,w1.w,acc[7]);
        acc[8]=fmaf(xv,w2.x,acc[8]);   acc[9]=fmaf(xv,w2.y,acc[9]);
        acc[10]=fmaf(xv,w2.z,acc[10]); acc[11]=fmaf(xv,w2.w,acc[11]);
        acc[12]=fmaf(xv,w3.x,acc[12]); acc[13]=fmaf(xv,w3.y,acc[13]);
        acc[14]=fmaf(xv,w3.z,acc[14]); acc[15]=fmaf(xv,w3.w,acc[15]);
    }
    int m = m0 + r;
    #pragma unroll
    for (int j = 0; j < 16; j++){
        int h = hg*16 + j;
        g_pt[(size_t)m*Hz + h] = wrap_pi(acc[j] + be[h]);
    }
}

// ============================ 2) repeat flags ============================
__global__ void zero_kernel(){ g_anyrep = 0; }

__global__ void rep_kernel(const float* __restrict__ x){
    int s = blockIdx.x;
    int ok;
    if (s > 0){
        ok = 1;
        for (int i = threadIdx.x; i < Bz*Dz; i += 256){
            int b = i >> 6, d = i & 63;
            size_t idx = ((size_t)b*Sz + s)*Dz + d;
            if (x[idx] != x[idx - Dz]) { ok = 0; break; }
        }
    } else ok = 0;
    ok = __syncthreads_and(ok);
    if (threadIdx.x == 0){
        g_rep[s] = ok;
        if (ok) atomicOr(&g_anyrep, 1);
    }
}

// ============================ 3) recurrence ============================
__global__ __launch_bounds__(128) void recur_kernel(const float* __restrict__ omega,
                                                    float* __restrict__ out_ph,
                                                    float* __restrict__ out_wb){
    __shared__ float tbl[Sz];
    __shared__ int   reps[Sz];
    __shared__ int   any8[Sz/8];
    int b = blockIdx.x, h = threadIdx.x;
    for (int i = h; i < Sz; i += 128){
        reps[i] = g_rep[i];
        tbl[i]  = 0.25f*fsin(0.015625f*(float)(i+1));
    }
    __syncthreads();
    for (int i = h; i < Sz/8; i += 128){
        int a = 0;
        #pragma unroll
        for (int j = 0; j < 8; j++) a |= reps[i*8 + j];
        any8[i] = a;
    }
    __syncthreads();

    float om = omega[h];
    float ph = 0.f, phw = 0.f, wb = 0.f;
    bool div = false;
    const float* ptp = g_pt + (size_t)b*Sz*Hz + h;
    float* php = out_ph + (size_t)b*Sz*Hz + h;
    float* wbp = out_wb + (size_t)b*Sz*Hz + h;

    for (int s0 = 0; s0 < Sz; s0 += 8){
        float pts[8];
        #pragma unroll
        for (int j = 0; j < 8; j++) pts[j] = ptp[(size_t)(s0 + j)*Hz];
        if (!div && !any8[s0 >> 3]){
            #pragma unroll
            for (int j = 0; j < 8; j++){
                int s = s0 + j;
                wb += 0.015625f;
                float c = om + tbl[s];
                float t = c - __sinf(pts[j] - phw);
                ph  += t;
                phw += t;
                float k = fmaf(phw, 0.15915494309189535f, 12582912.0f) - 12582912.0f;
                phw = fmaf(k, -6.28125f, phw);
                phw = fmaf(k, -1.9353071795864769e-3f, phw);
                php[(size_t)s*Hz] = ph;
                wbp[(size_t)s*Hz] = wb;
            }
        } else {
            #pragma unroll
            for (int j = 0; j < 8; j++){
                int s = s0 + j;
                wb += 0.015625f;
                float c = om + 0.25f*fsin(wb);
                float t = c - __sinf(pts[j] - phw);
                float phn  = ph + t;
                float phwn = phw + t;
                if (reps[s]) { wb += 0.25f*fsin(pts[j] - wb); div = true; }
                ph = phn; phw = phwn;
                float k = fmaf(phw, 0.15915494309189535f, 12582912.0f) - 12582912.0f;
                phw = fmaf(k, -6.28125f, phw);
                phw = fmaf(k, -1.9353071795864769e-3f, phw);
                php[(size_t)s*Hz] = ph;
                wbp[(size_t)s*Hz] = wb;
            }
        }
    }
}

// ============================ 4) weight prep ============================
__global__ void bperm_kernel(const float* __restrict__ Wr){
    int i = blockIdx.x*256 + threadIdx.x;
    if (i < Oz*Kz){
        int n = i >> 10, k = i & 1023;
        int h = k >> 3, jf = k & 7;
        if (jf > 6) jf = 6;
        g_Bp[i] = __float2half(Wr[n*(7*Hz) + jf*Hz + h]);
    }
}
__global__ void bperm4_kernel(const float* __restrict__ Wr){
    int i = blockIdx.x*256 + threadIdx.x;
    if (i < Oz*512){
        int n = i >> 9, k = i & 511;
        int h = k >> 2, jf = k & 3;
        g_Bp4[i] = __float2half(Wr[n*(7*Hz) + jf*Hz + h]);
    }
}
__global__ void b6_kernel(const float* __restrict__ Wr){
    int i = blockIdx.x*256 + threadIdx.x;
    if (i < Hz*Oz){
        int h = i >> 9, n = i & 511;
        g_B6[i] = Wr[n*(7*Hz) + 6*Hz + h];
    }
}
__global__ void w45_kernel(const float* __restrict__ Wr){
    int n = blockIdx.x*256 + threadIdx.x;
    if (n < Oz){
        float s4 = 0.f, s5 = 0.f;
        for (int h = 0; h < Hz; h++){
            s4 += Wr[n*(7*Hz) + 4*Hz + h];
            s5 += Wr[n*(7*Hz) + 5*Hz + h];
        }
        g_W45[n] = s4; g_W45[Oz + n] = s5;
    }
}

// ============================ 5) fused readout GEMM ============================
// Fast (no repeats):  K=512 HMMA (4 trig planes) + ph term via FFMA2 + wb rank-2 epilogue.
// Slow (any repeat):  R9 K=1024 HMMA path, verbatim.
// fast smem: A 2x16K @0 | B 2x32K @32768 | w6 2x16K @98304 | ph 2x8K @131072 | brs @147456 | w45 @149504
#define RD_SMEM 151552

__global__ __launch_bounds__(256)
void readout_kernel(const float* __restrict__ ph_in, const float* __restrict__ wb_in,
                    const float* __restrict__ br, float* __restrict__ out){
    extern __shared__ __align__(128) char smem[];
    int t = threadIdx.x, wid = t >> 5, lane = t & 31;
    int n0 = blockIdx.x * 256, m0 = blockIdx.y * 128;
    int wm = wid & 3, wn = wid >> 2;               // warp tile: 32m x 128n

    int a_row = wm*32 + (lane & 7) + ((lane >> 3) & 1)*8;
    int a_kh  = (lane >> 4)*8;
    int b_row = wn*128 + (lane & 7) + (lane >> 4)*8;
    int b_kh  = ((lane >> 3) & 1)*8;
    int lr = lane >> 2, lc = (lane & 3)*2;

    __align__(16) float acc[2][16][4];
    #pragma unroll
    for (int mt = 0; mt < 2; mt++)
        #pragma unroll
        for (int nt = 0; nt < 16; nt++)
            #pragma unroll
            for (int v = 0; v < 4; v++) acc[mt][nt][v] = 0.f;

    if (!g_anyrep){
        // ======================= FAST PATH =======================
        char* Asm = smem;
        char* Bsm = smem + 32768;
        float* w6s = (float*)(smem + 98304);       // [buf][16h][256n]
        float* phs = (float*)(smem + 131072);      // [buf][16h][128m]
        float* brs = (float*)(smem + 147456);
        float* w45s= (float*)(smem + 149504);      // [2][256]

        for (int i = t; i < Oz; i += 256) brs[i] = br[i];
        for (int i = t; i < 256; i += 256){
            w45s[i]       = g_W45[n0 + i];
            w45s[256 + i] = g_W45[Oz + n0 + i];
        }

        uint32_t As_b = smem_u32(Asm), Bs_b = smem_u32(Bsm);
        uint32_t W6_b = smem_u32(w6s), PH_b = smem_u32(phs);
        const uint4* bsrc = (const uint4*)g_Bp4;
        const uint4* wsrc = (const uint4*)g_B6;
        int bn = t >> 3, bk16 = t & 7;             // B: 256n x 8 x16B per chunk
        int gm = t & 127, gtb = t >> 7;            // A-gen: row, hl parity

        // ---- prologue: chunk 0 ----
        {
            #pragma unroll
            for (int it = 0; it < 8; it++){
                int n = bn + it*32;
                cp_async16(Bs_b + swz((uint32_t)(n*128 + bk16*16)),
                           &bsrc[(size_t)(n0 + n)*64 + bk16]);
            }
            // w6 chunk0: 16h x 256n fp32 = 1024 x16B
            #pragma unroll
            for (int it = 0; it < 4; it++){
                int i = t + it*256;
                int hh = i >> 6, nn = (i & 63)*4;
                cp_async16(W6_b + (uint32_t)((hh*256 + nn)*4),
                           &wsrc[(size_t)hh*128 + (n0 + nn)/4]);
            }
            CP_COMMIT();
            #pragma unroll
            for (int it = 0; it < 8; it++){
                int hl = gtb + it*2;
                float ph = ph_in[(size_t)(m0 + gm)*Hz + hl];
                float s2, c2; fsincos(0.5f*ph, &s2, &c2);
                float c1 = fmaf(2.f*c2, c2, -1.f);
                float s1 = 2.f*s2*c2;
                uint2 v;
                v.x = h2_to_u32(__floats2half2_rn(c1, s1));
                v.y = h2_to_u32(__floats2half2_rn(c2, s2));
                *(uint2*)(Asm + swz((uint32_t)(gm*128 + hl*8))) = v;
                phs[hl*128 + gm] = ph;
            }
            CP_WAIT0();
            __syncthreads();
        }

        for (int c = 0; c < 8; c++){
            int cur = c & 1, nxt = cur ^ 1;
            float pr[8];
            if (c < 7){
                #pragma unroll
                for (int it = 0; it < 8; it++){
                    int n = bn + it*32;
                    cp_async16(Bs_b + (uint32_t)(nxt*32768) + swz((uint32_t)(n*128 + bk16*16)),
                               &bsrc[(size_t)(n0 + n)*64 + (c+1)*8 + bk16]);
                }
                #pragma unroll
                for (int it = 0; it < 4; it++){
                    int i = t + it*256;
                    int hh = i >> 6, nn = (i & 63)*4;
                    cp_async16(W6_b + (uint32_t)((nxt*4096 + hh*256 + nn)*4),
                               &wsrc[(size_t)((c+1)*16 + hh)*128 + (n0 + nn)/4]);
                }
                CP_COMMIT();
                #pragma unroll
                for (int it = 0; it < 8; it++){
                    int hl = gtb + it*2;
                    pr[it] = ph_in[(size_t)(m0 + gm)*Hz + (c+1)*16 + hl];
                }
            }
            // ---- MMA on cur ----
            uint32_t Ab = As_b + (uint32_t)(cur*16384);
            uint32_t Bb = Bs_b + (uint32_t)(cur*32768);
            #pragma unroll
            for (int ks = 0; ks < 4; ks++){
                uint32_t af[2][4];
                #pragma unroll
                for (int mt = 0; mt < 2; mt++)
                    ldsm_x4(af[mt], Ab + swz((uint32_t)((a_row + mt*16)*128 + (ks*16 + a_kh)*2)));
                uint32_t bf[8][4];
                #pragma unroll
                for (int ntp = 0; ntp < 8; ntp++)
                    ldsm_x4(bf[ntp], Bb + swz((uint32_t)((b_row + ntp*16)*128 + (ks*16 + b_kh)*2)));
                #pragma unroll
                for (int mt = 0; mt < 2; mt++)
                    #pragma unroll
                    for (int nt = 0; nt < 16; nt++)
                        mma16816(acc[mt][nt], af[mt], &bf[nt >> 1][(nt & 1)*2]);
            }
            // ---- ph term FFMA2 on cur (fma pipe, hidden under HMMA) ----
            {
                const float* phc = phs + cur*2048;
                const float* w6c = w6s + cur*4096;
                #pragma unroll 2
                for (int hl = 0; hl < 16; hl++){
                    float p0 = phc[hl*128 + wm*32 + lr];
                    float p1 = phc[hl*128 + wm*32 + lr + 8];
                    float p2 = phc[hl*128 + wm*32 + lr + 16];
                    float p3 = phc[hl*128 + wm*32 + lr + 24];
                    const float* wrow = w6c + hl*256 + wn*128 + lc;
                    #pragma unroll
                    for (int nt = 0; nt < 16; nt++){
                        float2 w = *(const float2*)(wrow + nt*8);
                        ffma2((float2*)&acc[0][nt][0], make_float2(p0, p0), w);
                        ffma2((float2*)&acc[0][nt][2], make_float2(p1, p1), w);
                        ffma2((float2*)&acc[1][nt][0], make_float2(p2, p2), w);
                        ffma2((float2*)&acc[1][nt][2], make_float2(p3, p3), w);
                    }
                }
            }
            if (c < 7){
                #pragma unroll
                for (int it = 0; it < 8; it++){
                    int hl = gtb + it*2;
                    float ph = pr[it];
                    float s2, c2; fsincos(0.5f*ph, &s2, &c2);
                    float c1 = fmaf(2.f*c2, c2, -1.f);
                    float s1 = 2.f*s2*c2;
                    uint2 v;
                    v.x = h2_to_u32(__floats2half2_rn(c1, s1));
                    v.y = h2_to_u32(__floats2half2_rn(c2, s2));
                    *(uint2*)(Asm + nxt*16384 + swz((uint32_t)(gm*128 + hl*8))) = v;
                    phs[nxt*2048 + hl*128 + gm] = ph;
                }
                CP_WAIT0();
            }
            __syncthreads();
        }

        // ---- epilogue: wb rank-2 + bias ----
        float cw[4], sw[4];
        #pragma unroll
        for (int j = 0; j < 4; j++){
            int m = m0 + wm*32 + j*8 + lr;
            int s = m & (Sz - 1);
            float wbv = (float)(s + 1) * 0.015625f;
            fsincos(wbv, &sw[j], &cw[j]);
        }
        #pragma unroll
        for (int mt = 0; mt < 2; mt++){
            #pragma unroll
            for (int nt = 0; nt < 16; nt++){
                int n = n0 + wn*128 + nt*8 + lc;
                int ln = wn*128 + nt*8 + lc;
                float w40 = w45s[ln], w41 = w45s[ln+1];
                float w50 = w45s[256+ln], w51 = w45s[256+ln+1];
                int m = m0 + wm*32 + mt*16 + lr;
                float b0 = brs[n], b1 = brs[n+1];
                float r0 = acc[mt][nt][0] + cw[mt*2]*w40 + sw[mt*2]*w50 + b0;
                float r1 = acc[mt][nt][1] + cw[mt*2]*w41 + sw[mt*2]*w51 + b1;
                float r2 = acc[mt][nt][2] + cw[mt*2+1]*w40 + sw[mt*2+1]*w50 + b0;
                float r3 = acc[mt][nt][3] + cw[mt*2+1]*w41 + sw[mt*2+1]*w51 + b1;
                *(float2*)&out[(size_t)m*Oz + n]       = make_float2(r0, r1);
                *(float2*)&out[(size_t)(m + 8)*Oz + n] = make_float2(r2, r3);
            }
        }
    } else {
        // ======================= SLOW PATH (R9 verbatim, K=1024) =======================
        char* Asm = smem;
        char* Bsm = smem + 32768;
        float* brs = (float*)(smem + 98304);
        for (int i = t; i < Oz; i += 256) brs[i] = br[i];
        uint32_t As_b = smem_u32(Asm), Bs_b = smem_u32(Bsm);
        int gm = t >> 3, ghl = t & 7;
        const uint4* bsrc = (const uint4*)g_Bp;
        int bn = t >> 3, bk16 = t & 7;
        {
            #pragma unroll
            for (int it = 0; it < 8; it++){
                int n = bn + it*32;
                cp_async16(Bs_b + swz((uint32_t)(n*128 + bk16*16)),
                           &bsrc[(size_t)(n0 + n)*128 + bk16]);
            }
            CP_COMMIT();
            #pragma unroll
            for (int it = 0; it < 4; it++){
                int m = gm + it*32, h = ghl;
                float ph = ph_in[(size_t)(m0 + m)*Hz + h];
                float wb = wb_in[(size_t)(m0 + m)*Hz + h];
                float s2, c2; fsincos(0.5f*ph, &s2, &c2);
                float c1 = fmaf(2.f*c2, c2, -1.f);
                float s1 = 2.f*s2*c2;
                float s3, c3; fsincos(wb, &s3, &c3);
                __half hhi = __float2half(ph);
                __half hlo = __float2half(ph - __half2float(hhi));
                uint4 v;
                v.x = h2_to_u32(__floats2half2_rn(c1, s1));
                v.y = h2_to_u32(__floats2half2_rn(c2, s2));
                v.z = h2_to_u32(__floats2half2_rn(c3, s3));
                v.w = h2_to_u32(__halves2half2(hhi, hlo));
                *(uint4*)(Asm + swz((uint32_t)(m*128 + ghl*16))) = v;
            }
            CP_WAIT0();
            __syncthreads();
        }
        for (int c = 0; c < 16; c++){
            int cur = c & 1, nxt = cur ^ 1;
            float pr[4], wr[4];
            if (c < 15){
                #pragma unroll
                for (int it = 0; it < 8; it++){
                    int n = bn + it*32;
                    cp_async16(Bs_b + (uint32_t)(nxt*32768) + swz((uint32_t)(n*128 + bk16*16)),
                               &bsrc[(size_t)(n0 + n)*128 + (c+1)*8 + bk16]);
                }
                CP_COMMIT();
                int h = (c+1)*8 + ghl;
                #pragma unroll
                for (int it = 0; it < 4; it++){
                    int m = gm + it*32;
                    pr[it] = ph_in[(size_t)(m0 + m)*Hz + h];
                    wr[it] = wb_in[(size_t)(m0 + m)*Hz + h];
                }
            }
            uint32_t Ab = As_b + (uint32_t)(cur*16384);
            uint32_t Bb = Bs_b + (uint32_t)(cur*32768);
            #pragma unroll
            for (int ks = 0; ks < 4; ks++){
                uint32_t af[2][4];
                #pragma unroll
                for (int mt = 0; mt < 2; mt++)
                    ldsm_x4(af[mt], Ab + swz((uint32_t)((a_row + mt*16)*128 + (ks*16 + a_kh)*2)));
                uint32_t bf[8][4];
                #pragma unroll
                for (int ntp = 0; ntp < 8; ntp++)
                    ldsm_x4(bf[ntp], Bb + swz((uint32_t)((b_row + ntp*16)*128 + (ks*16 + b_kh)*2)));
                #pragma unroll
                for (int mt = 0; mt < 2; mt++)
                    #pragma unroll
                    for (int nt = 0; nt < 16; nt++)
                        mma16816(acc[mt][nt], af[mt], &bf[nt >> 1][(nt & 1)*2]);
            }
            if (c < 15){
                #pragma unroll
                for (int it = 0; it < 4; it++){
                    int m = gm + it*32;
                    float ph = pr[it], wb = wr[it];
                    float s2, c2; fsincos(0.5f*ph, &s2, &c2);
                    float c1 = fmaf(2.f*c2, c2, -1.f);
                    float s1 = 2.f*s2*c2;
                    float s3, c3; fsincos(wb, &s3, &c3);
                    __half hhi = __float2half(ph);
                    __half hlo = __float2half(ph - __half2float(hhi));
                    uint4 v;
                    v.x = h2_to_u32(__floats2half2_rn(c1, s1));
                    v.y = h2_to_u32(__floats2half2_rn(c2, s2));
                    v.z = h2_to_u32(__floats2half2_rn(c3, s3));
                    v.w = h2_to_u32(__halves2half2(hhi, hlo));
                    *(uint4*)(Asm + nxt*16384 + swz((uint32_t)(m*128 + ghl*16))) = v;
                }
                CP_WAIT0();
            }
            __syncthreads();
        }
        #pragma unroll
        for (int mt = 0; mt < 2; mt++){
            #pragma unroll
            for (int nt = 0; nt < 16; nt++){
                int m = m0 + wm*32 + mt*16 + lr;
                int n = n0 + wn*128 + nt*8 + lc;
                float b0 = brs[n], b1 = brs[n + 1];
                *(float2*)&out[(size_t)m*Oz + n]       = make_float2(acc[mt][nt][0] + b0, acc[mt][nt][1] + b1);
                *(float2*)&out[(size_t)(m + 8)*Oz + n] = make_float2(acc[mt][nt][2] + b0, acc[mt][nt][3] + b1);
            }
        }
    }
}

// ============================ launch ============================
extern "C" void kernel_launch(void* const* d_in, const int* in_sizes, int n_in,
                              void* d_out, int out_size){
    const float* x     = (const float*)d_in[0];
    const float* We    = (const float*)d_in[1];
    const float* be    = (const float*)d_in[2];
    const float* omega = (const float*)d_in[3];
    const float* Wr    = (const float*)d_in[4];
    const float* br    = (const float*)d_in[5];
    float* out        = (float*)d_out;
    float* out_logits = out;                       // [B,S,O]
    float* out_ph     = out + (size_t)Mz*Oz;       // [B,S,H]
    float* out_wb     = out_ph + (size_t)Mz*Hz;    // [B,S,H]

    cudaFuncSetAttribute(readout_kernel, cudaFuncAttributeMaxDynamicSharedMemorySize, RD_SMEM);

    encoder_kernel<<<Mz/32, 256>>>(x, We, be);
    zero_kernel<<<1, 1>>>();
    rep_kernel<<<Sz, 256>>>(x);
    bperm_kernel<<<(Oz*Kz + 255)/256, 256>>>(Wr);
    bperm4_kernel<<<(Oz*512 + 255)/256, 256>>>(Wr);
    b6_kernel<<<(Hz*Oz + 255)/256, 256>>>(Wr);
    w45_kernel<<<2, 256>>>(Wr);
    recur_kernel<<<Bz, 128>>>(omega, out_ph, out_wb);
    readout_kernel<<<dim3(Oz/256, Mz/128), 256, RD_SMEM>>>(out_ph, out_wb, br, out_logits);
}

// round 13
// speedup vs baseline: 1.0513x; 1.0513x over previous
#include <cuda_runtime.h>
#include <cuda_fp16.h>
#include <cstdint>

#define Bz 128
#define Sz 1024
#define Dz 64
#define Hz 128
#define Oz 512
#define Mz (Bz*Sz)   /* 131072 */
#define Kz 1024
#define PI_F 3.14159265358979f
#define TWO_PI_F 6.28318530717959f

// ---- static device scratch ----
__device__ float g_pt [(size_t)Mz*Hz];                  // encoder output, PRE-WRAPPED
__device__ __align__(16) __half g_Bp [(size_t)Oz*Kz];   // 8-plane weights (slow path)
__device__ __align__(16) __half g_Bp4[(size_t)Oz*512];  // 4 trig planes (fast path) [n][h*4+jf]
__device__ __align__(16) __half g_Bp6[(size_t)Oz*256];  // ph hi/lo planes [n][h*2+j] (both = w6)
__device__ float g_W45[2*Oz];                           // column sums of w4, w5
__device__ int   g_rep[Sz];
__device__ int   g_anyrep;

// ============================ helpers ============================
__device__ __forceinline__ uint32_t h2_to_u32(__half2 v){
    return *reinterpret_cast<uint32_t*>(&v);
}
__device__ __forceinline__ uint32_t smem_u32(const void* p){
    uint32_t a;
    asm("{ .reg .u64 t; cvta.to.shared.u64 t, %1; cvt.u32.u64 %0, t; }" : "=r"(a) : "l"(p));
    return a;
}
__device__ __forceinline__ uint32_t swz(uint32_t b){ return b ^ ((b >> 3) & 0x70); }

__device__ __forceinline__ void ldsm_x4(uint32_t* r, uint32_t addr){
    asm volatile("ldmatrix.sync.aligned.m8n8.x4.shared.b16 {%0,%1,%2,%3}, [%4];"
        : "=r"(r[0]), "=r"(r[1]), "=r"(r[2]), "=r"(r[3]) : "r"(addr));
}
__device__ __forceinline__ void mma16816(float* d, const uint32_t* a, const uint32_t* b){
    asm volatile("mma.sync.aligned.m16n8k16.row.col.f32.f16.f16.f32 "
        "{%0,%1,%2,%3}, {%4,%5,%6,%7}, {%8,%9}, {%0,%1,%2,%3};"
        : "+f"(d[0]), "+f"(d[1]), "+f"(d[2]), "+f"(d[3])
        : "r"(a[0]), "r"(a[1]), "r"(a[2]), "r"(a[3]), "r"(b[0]), "r"(b[1]));
}
__device__ __forceinline__ void cp_async16(uint32_t dst, const void* src){
    asm volatile("cp.async.cg.shared.global [%0], [%1], 16;" :: "r"(dst), "l"(src));
}
#define CP_COMMIT() asm volatile("cp.async.commit_group;" ::: "memory")
#define CP_WAIT0()  asm volatile("cp.async.wait_group 0;" ::: "memory")

// ---- fast sin/sincos with magic-number range reduction ----
__device__ __forceinline__ float wrap_pi(float x){
    float k = fmaf(x, 0.15915494309189535f, 12582912.0f);
    k -= 12582912.0f;
    float r = fmaf(k, -6.28125f, x);
    r = fmaf(k, -1.9353071795864769e-3f, r);
    return r;
}
__device__ __forceinline__ float fsin(float x){ return __sinf(wrap_pi(x)); }
__device__ __forceinline__ void fsincos(float x, float* s, float* c){ __sincosf(wrap_pi(x), s, c); }

// ============================ 1) encoder (stores wrapped pt) ============================
__global__ __launch_bounds__(256) void encoder_kernel(const float* __restrict__ x,
                                                      const float* __restrict__ We,
                                                      const float* __restrict__ be){
    __shared__ __align__(16) float WeT[Dz*Hz];
    __shared__ float xs[32*Dz];
    int t = threadIdx.x;
    int m0 = blockIdx.x * 32;
    for (int i = t; i < Dz*Hz; i += 256){ int h = i >> 6, k = i & 63; WeT[k*Hz + h] = We[i]; }
    for (int i = t; i < 32*Dz; i += 256) xs[i] = x[(size_t)m0*Dz + i];
    __syncthreads();
    int r = t >> 3, hg = t & 7;
    float acc[16];
    #pragma unroll
    for (int j = 0; j < 16; j++) acc[j] = 0.f;
    #pragma unroll 4
    for (int k = 0; k < Dz; k++){
        float xv = xs[r*Dz + k];
        const float4* wp = (const float4*)&WeT[k*Hz + hg*16];
        float4 w0 = wp[0], w1 = wp[1], w2 = wp[2], w3 = wp[3];
        acc[0]=fmaf(xv,w0.x,acc[0]);   acc[1]=fmaf(xv,w0.y,acc[1]);
        acc[2]=fmaf(xv,w0.z,acc[2]);   acc[3]=fmaf(xv,w0.w,acc[3]);
        acc[4]=fmaf(xv,w1.x,acc[4]);   acc[5]=fmaf(xv,w1.y,acc[5]);
        acc[6]=fmaf(xv,w1.z,acc[6]);   acc[7]=fmaf(xv,w1.w,acc[7]);
        acc[8]=fmaf(xv,w2.x,acc[8]);   acc[9]=fmaf(xv,w2.y,acc[9]);
        acc[10]=fmaf(xv,w2.z,acc[10]); acc[11]=fmaf(xv,w2.w,acc[11]);
        acc[12]=fmaf(xv,w3.x,acc[12]); acc[13]=fmaf(xv,w3.y,acc[13]);
        acc[14]=fmaf(xv,w3.z,acc[14]); acc[15]=fmaf(xv,w3.w,acc[15]);
    }
    int m = m0 + r;
    #pragma unroll
    for (int j = 0; j < 16; j++){
        int h = hg*16 + j;
        g_pt[(size_t)m*Hz + h] = wrap_pi(acc[j] + be[h]);
    }
}

// ============================ 2) repeat flags ============================
__global__ void zero_kernel(){ g_anyrep = 0; }

__global__ void rep_kernel(const float* __restrict__ x){
    int s = blockIdx.x;
    int ok;
    if (s > 0){
        ok = 1;
        for (int i = threadIdx.x; i < Bz*Dz; i += 256){
            int b = i >> 6, d = i & 63;
            size_t idx = ((size_t)b*Sz + s)*Dz + d;
            if (x[idx] != x[idx - Dz]) { ok = 0; break; }
        }
    } else ok = 0;
    ok = __syncthreads_and(ok);
    if (threadIdx.x == 0){
        g_rep[s] = ok;
        if (ok) atomicOr(&g_anyrep, 1);
    }
}

// ============================ 3) recurrence ============================
__global__ __launch_bounds__(128) void recur_kernel(const float* __restrict__ omega,
                                                    float* __restrict__ out_ph,
                                                    float* __restrict__ out_wb){
    __shared__ float tbl[Sz];
    __shared__ int   reps[Sz];
    __shared__ int   any8[Sz/8];
    int b = blockIdx.x, h = threadIdx.x;
    for (int i = h; i < Sz; i += 128){
        reps[i] = g_rep[i];
        tbl[i]  = 0.25f*fsin(0.015625f*(float)(i+1));
    }
    __syncthreads();
    for (int i = h; i < Sz/8; i += 128){
        int a = 0;
        #pragma unroll
        for (int j = 0; j < 8; j++) a |= reps[i*8 + j];
        any8[i] = a;
    }
    __syncthreads();

    float om = omega[h];
    float ph = 0.f, phw = 0.f, wb = 0.f;
    bool div = false;
    const float* ptp = g_pt + (size_t)b*Sz*Hz + h;
    float* php = out_ph + (size_t)b*Sz*Hz + h;
    float* wbp = out_wb + (size_t)b*Sz*Hz + h;

    for (int s0 = 0; s0 < Sz; s0 += 8){
        float pts[8];
        #pragma unroll
        for (int j = 0; j < 8; j++) pts[j] = ptp[(size_t)(s0 + j)*Hz];
        if (!div && !any8[s0 >> 3]){
            #pragma unroll
            for (int j = 0; j < 8; j++){
                int s = s0 + j;
                wb += 0.015625f;
                float c = om + tbl[s];
                float t = c - __sinf(pts[j] - phw);
                ph  += t;
                phw += t;
                float k = fmaf(phw, 0.15915494309189535f, 12582912.0f) - 12582912.0f;
                phw = fmaf(k, -6.28125f, phw);
                phw = fmaf(k, -1.9353071795864769e-3f, phw);
                php[(size_t)s*Hz] = ph;
                wbp[(size_t)s*Hz] = wb;
            }
        } else {
            #pragma unroll
            for (int j = 0; j < 8; j++){
                int s = s0 + j;
                wb += 0.015625f;
                float c = om + 0.25f*fsin(wb);
                float t = c - __sinf(pts[j] - phw);
                float phn  = ph + t;
                float phwn = phw + t;
                if (reps[s]) { wb += 0.25f*fsin(pts[j] - wb); div = true; }
                ph = phn; phw = phwn;
                float k = fmaf(phw, 0.15915494309189535f, 12582912.0f) - 12582912.0f;
                phw = fmaf(k, -6.28125f, phw);
                phw = fmaf(k, -1.9353071795864769e-3f, phw);
                php[(size_t)s*Hz] = ph;
                wbp[(size_t)s*Hz] = wb;
            }
        }
    }
}

// ============================ 4) weight prep ============================
__global__ void bperm_kernel(const float* __restrict__ Wr){
    int i = blockIdx.x*256 + threadIdx.x;
    if (i < Oz*Kz){
        int n = i >> 10, k = i & 1023;
        int h = k >> 3, jf = k & 7;
        if (jf > 6) jf = 6;
        g_Bp[i] = __float2half(Wr[n*(7*Hz) + jf*Hz + h]);
    }
}
__global__ void bperm4_kernel(const float* __restrict__ Wr){
    int i = blockIdx.x*256 + threadIdx.x;
    if (i < Oz*512){
        int n = i >> 9, k = i & 511;
        int h = k >> 2, jf = k & 3;
        g_Bp4[i] = __float2half(Wr[n*(7*Hz) + jf*Hz + h]);
    }
}
__global__ void bperm6_kernel(const float* __restrict__ Wr){
    int i = blockIdx.x*256 + threadIdx.x;
    if (i < Oz*256){
        int n = i >> 8, k = i & 255;
        int h = k >> 1;                       // both j slots get w6[h]
        g_Bp6[i] = __float2half(Wr[n*(7*Hz) + 6*Hz + h]);
    }
}
__global__ void w45_kernel(const float* __restrict__ Wr){
    int n = blockIdx.x*256 + threadIdx.x;
    if (n < Oz){
        float s4 = 0.f, s5 = 0.f;
        for (int h = 0; h < Hz; h++){
            s4 += Wr[n*(7*Hz) + 4*Hz + h];
            s5 += Wr[n*(7*Hz) + 5*Hz + h];
        }
        g_W45[n] = s4; g_W45[Oz + n] = s5;
    }
}

// ============================ 5) fused readout GEMM ============================
// Fast (no repeats):  12 K-chunks of 64: c<8 trig planes (K=512), c>=8 ph hi/lo (K=256);
//                     wb features via exact rank-2 epilogue.
// Slow (any repeat):  R9 K=1024 path, verbatim.
// smem: A 2x16K @0 | B 2x32K @32768 | brs @98304 | w45 @100352
#define RD_SMEM 102400

__global__ __launch_bounds__(256)
void readout_kernel(const float* __restrict__ ph_in, const float* __restrict__ wb_in,
                    const float* __restrict__ br, float* __restrict__ out){
    extern __shared__ __align__(128) char smem[];
    int t = threadIdx.x, wid = t >> 5, lane = t & 31;
    int n0 = blockIdx.x * 256, m0 = blockIdx.y * 128;
    int wm = wid & 3, wn = wid >> 2;               // warp tile: 32m x 128n

    int a_row = wm*32 + (lane & 7) + ((lane >> 3) & 1)*8;
    int a_kh  = (lane >> 4)*8;
    int b_row = wn*128 + (lane & 7) + (lane >> 4)*8;
    int b_kh  = ((lane >> 3) & 1)*8;
    int lr = lane >> 2, lc = (lane & 3)*2;

    char* Asm = smem;
    char* Bsm = smem + 32768;
    float* brs  = (float*)(smem + 98304);
    float* w45s = (float*)(smem + 100352);

    uint32_t As_b = smem_u32(Asm), Bs_b = smem_u32(Bsm);

    __align__(16) float acc[2][16][4];
    #pragma unroll
    for (int mt = 0; mt < 2; mt++)
        #pragma unroll
        for (int nt = 0; nt < 16; nt++)
            #pragma unroll
            for (int v = 0; v < 4; v++) acc[mt][nt][v] = 0.f;

    for (int i = t; i < Oz; i += 256) brs[i] = br[i];

    if (!g_anyrep){
        // ======================= FAST PATH (12 chunks) =======================
        if (t < 256){
            w45s[t]       = g_W45[n0 + t];
            w45s[256 + t] = g_W45[Oz + n0 + t];
        }
        const uint4* b4 = (const uint4*)g_Bp4;
        const uint4* b6 = (const uint4*)g_Bp6;
        int bn = t >> 3, bk16 = t & 7;             // B: 256n rows x 8 x16B per chunk
        int gm = t & 127, gtb = t >> 7;            // A-gen: m row, slot parity

        // ---- A generator for chunk c into buffer buf ----
        auto genA = [&](int c, int buf){
            char* As = Asm + buf*16384;
            if (c < 8){
                #pragma unroll
                for (int it = 0; it < 8; it++){
                    int hl = gtb + it*2;                         // 0..15
                    float ph = __ldg(&ph_in[(size_t)(m0 + gm)*Hz + c*16 + hl]);
                    float s2, c2; fsincos(0.5f*ph, &s2, &c2);
                    float c1 = fmaf(2.f*c2, c2, -1.f);
                    float s1 = 2.f*s2*c2;
                    uint2 v;
                    v.x = h2_to_u32(__floats2half2_rn(c1, s1));
                    v.y = h2_to_u32(__floats2half2_rn(c2, s2));
                    *(uint2*)(As + swz((uint32_t)(gm*128 + hl*8))) = v;
                }
            } else {
                int pc = c - 8;
                #pragma unroll
                for (int it = 0; it < 8; it++){
                    int pp = gtb + it*2;                         // h-pair 0..15
                    int h0 = pc*32 + pp*2;
                    float p0 = __ldg(&ph_in[(size_t)(m0 + gm)*Hz + h0]);
                    float p1 = __ldg(&ph_in[(size_t)(m0 + gm)*Hz + h0 + 1]);
                    __half h0i = __float2half(p0);
                    __half h0l = __float2half(p0 - __half2float(h0i));
                    __half h1i = __float2half(p1);
                    __half h1l = __float2half(p1 - __half2float(h1i));
                    uint2 v;
                    v.x = h2_to_u32(__halves2half2(h0i, h0l));
                    v.y = h2_to_u32(__halves2half2(h1i, h1l));
                    *(uint2*)(As + swz((uint32_t)(gm*128 + pp*8))) = v;
                }
            }
        };
        // ---- B loader for chunk c into buffer buf (async) ----
        auto loadB = [&](int c, int buf){
            #pragma unroll
            for (int it = 0; it < 8; it++){
                int n = bn + it*32;
                const void* src = (c < 8)
                    ? (const void*)&b4[(size_t)(n0 + n)*64 + c*8 + bk16]
                    : (const void*)&b6[(size_t)(n0 + n)*32 + (c - 8)*8 + bk16];
                cp_async16(Bs_b + (uint32_t)(buf*32768) + swz((uint32_t)(n*128 + bk16*16)), src);
            }
            CP_COMMIT();
        };

        // prologue
        loadB(0, 0);
        genA(0, 0);
        CP_WAIT0();
        __syncthreads();

        for (int c = 0; c < 12; c++){
            int cur = c & 1, nxt = cur ^ 1;
            if (c < 11) loadB(c + 1, nxt);
            // ---- MMA on cur ----
            uint32_t Ab = As_b + (uint32_t)(cur*16384);
            uint32_t Bb = Bs_b + (uint32_t)(cur*32768);
            #pragma unroll
            for (int ks = 0; ks < 4; ks++){
                uint32_t af[2][4];
                #pragma unroll
                for (int mt = 0; mt < 2; mt++)
                    ldsm_x4(af[mt], Ab + swz((uint32_t)((a_row + mt*16)*128 + (ks*16 + a_kh)*2)));
                uint32_t bf[8][4];
                #pragma unroll
                for (int ntp = 0; ntp < 8; ntp++)
                    ldsm_x4(bf[ntp], Bb + swz((uint32_t)((b_row + ntp*16)*128 + (ks*16 + b_kh)*2)));
                #pragma unroll
                for (int mt = 0; mt < 2; mt++)
                    #pragma unroll
                    for (int nt = 0; nt < 16; nt++)
                        mma16816(acc[mt][nt], af[mt], &bf[nt >> 1][(nt & 1)*2]);
            }
            if (c < 11){
                genA(c + 1, nxt);
                CP_WAIT0();
            }
            __syncthreads();
        }

        // ---- epilogue: wb rank-2 + bias ----
        float cw[4], sw[4];
        #pragma unroll
        for (int j = 0; j < 4; j++){
            int m = m0 + wm*32 + j*8 + lr;
            int s = m & (Sz - 1);
            float wbv = (float)(s + 1) * 0.015625f;
            fsincos(wbv, &sw[j], &cw[j]);
        }
        #pragma unroll
        for (int mt = 0; mt < 2; mt++){
            #pragma unroll
            for (int nt = 0; nt < 16; nt++){
                int ln = wn*128 + nt*8 + lc;
                int n  = n0 + ln;
                float w40 = w45s[ln],     w41 = w45s[ln+1];
                float w50 = w45s[256+ln], w51 = w45s[256+ln+1];
                int m = m0 + wm*32 + mt*16 + lr;
                float b0 = brs[n], b1 = brs[n+1];
                float r0 = acc[mt][nt][0] + cw[mt*2]*w40 + sw[mt*2]*w50 + b0;
                float r1 = acc[mt][nt][1] + cw[mt*2]*w41 + sw[mt*2]*w51 + b1;
                float r2 = acc[mt][nt][2] + cw[mt*2+1]*w40 + sw[mt*2+1]*w50 + b0;
                float r3 = acc[mt][nt][3] + cw[mt*2+1]*w41 + sw[mt*2+1]*w51 + b1;
                *(float2*)&out[(size_t)m*Oz + n]       = make_float2(r0, r1);
                *(float2*)&out[(size_t)(m + 8)*Oz + n] = make_float2(r2, r3);
            }
        }
    } else {
        // ======================= SLOW PATH (K=1024, R9 verbatim) =======================
        uint32_t As_bl = As_b, Bs_bl = Bs_b;
        int gm = t >> 3, ghl = t & 7;
        const uint4* bsrc = (const uint4*)g_Bp;
        int bn = t >> 3, bk16 = t & 7;
        {
            #pragma unroll
            for (int it = 0; it < 8; it++){
                int n = bn + it*32;
                cp_async16(Bs_bl + swz((uint32_t)(n*128 + bk16*16)),
                           &bsrc[(size_t)(n0 + n)*128 + bk16]);
            }
            CP_COMMIT();
            #pragma unroll
            for (int it = 0; it < 4; it++){
                int m = gm + it*32, h = ghl;
                float ph = ph_in[(size_t)(m0 + m)*Hz + h];
                float wb = wb_in[(size_t)(m0 + m)*Hz + h];
                float s2, c2; fsincos(0.5f*ph, &s2, &c2);
                float c1 = fmaf(2.f*c2, c2, -1.f);
                float s1 = 2.f*s2*c2;
                float s3, c3; fsincos(wb, &s3, &c3);
                __half hhi = __float2half(ph);
                __half hlo = __float2half(ph - __half2float(hhi));
                uint4 v;
                v.x = h2_to_u32(__floats2half2_rn(c1, s1));
                v.y = h2_to_u32(__floats2half2_rn(c2, s2));
                v.z = h2_to_u32(__floats2half2_rn(c3, s3));
                v.w = h2_to_u32(__halves2half2(hhi, hlo));
                *(uint4*)(Asm + swz((uint32_t)(m*128 + ghl*16))) = v;
            }
            CP_WAIT0();
            __syncthreads();
        }
        for (int c = 0; c < 16; c++){
            int cur = c & 1, nxt = cur ^ 1;
            float pr[4], wr[4];
            if (c < 15){
                #pragma unroll
                for (int it = 0; it < 8; it++){
                    int n = bn + it*32;
                    cp_async16(Bs_bl + (uint32_t)(nxt*32768) + swz((uint32_t)(n*128 + bk16*16)),
                               &bsrc[(size_t)(n0 + n)*128 + (c+1)*8 + bk16]);
                }
                CP_COMMIT();
                int h = (c+1)*8 + ghl;
                #pragma unroll
                for (int it = 0; it < 4; it++){
                    int m = gm + it*32;
                    pr[it] = ph_in[(size_t)(m0 + m)*Hz + h];
                    wr[it] = wb_in[(size_t)(m0 + m)*Hz + h];
                }
            }
            uint32_t Ab = As_bl + (uint32_t)(cur*16384);
            uint32_t Bb = Bs_bl + (uint32_t)(cur*32768);
            #pragma unroll
            for (int ks = 0; ks < 4; ks++){
                uint32_t af[2][4];
                #pragma unroll
                for (int mt = 0; mt < 2; mt++)
                    ldsm_x4(af[mt], Ab + swz((uint32_t)((a_row + mt*16)*128 + (ks*16 + a_kh)*2)));
                uint32_t bf[8][4];
                #pragma unroll
                for (int ntp = 0; ntp < 8; ntp++)
                    ldsm_x4(bf[ntp], Bb + swz((uint32_t)((b_row + ntp*16)*128 + (ks*16 + b_kh)*2)));
                #pragma unroll
                for (int mt = 0; mt < 2; mt++)
                    #pragma unroll
                    for (int nt = 0; nt < 16; nt++)
                        mma16816(acc[mt][nt], af[mt], &bf[nt >> 1][(nt & 1)*2]);
            }
            if (c < 15){
                #pragma unroll
                for (int it = 0; it < 4; it++){
                    int m = gm + it*32;
                    float ph = pr[it], wb = wr[it];
                    float s2, c2; fsincos(0.5f*ph, &s2, &c2);
                    float c1 = fmaf(2.f*c2, c2, -1.f);
                    float s1 = 2.f*s2*c2;
                    float s3, c3; fsincos(wb, &s3, &c3);
                    __half hhi = __float2half(ph);
                    __half hlo = __float2half(ph - __half2float(hhi));
                    uint4 v;
                    v.x = h2_to_u32(__floats2half2_rn(c1, s1));
                    v.y = h2_to_u32(__floats2half2_rn(c2, s2));
                    v.z = h2_to_u32(__floats2half2_rn(c3, s3));
                    v.w = h2_to_u32(__halves2half2(hhi, hlo));
                    *(uint4*)(Asm + nxt*16384 + swz((uint32_t)(m*128 + ghl*16))) = v;
                }
                CP_WAIT0();
            }
            __syncthreads();
        }
        #pragma unroll
        for (int mt = 0; mt < 2; mt++){
            #pragma unroll
            for (int nt = 0; nt < 16; nt++){
                int m = m0 + wm*32 + mt*16 + lr;
                int n = n0 + wn*128 + nt*8 + lc;
                float b0 = brs[n], b1 = brs[n + 1];
                *(float2*)&out[(size_t)m*Oz + n]       = make_float2(acc[mt][nt][0] + b0, acc[mt][nt][1] + b1);
                *(float2*)&out[(size_t)(m + 8)*Oz + n] = make_float2(acc[mt][nt][2] + b0, acc[mt][nt][3] + b1);
            }
        }
    }
}

// ============================ launch ============================
extern "C" void kernel_launch(void* const* d_in, const int* in_sizes, int n_in,
                              void* d_out, int out_size){
    const float* x     = (const float*)d_in[0];
    const float* We    = (const float*)d_in[1];
    const float* be    = (const float*)d_in[2];
    const float* omega = (const float*)d_in[3];
    const float* Wr    = (const float*)d_in[4];
    const float* br    = (const float*)d_in[5];
    float* out        = (float*)d_out;
    float* out_logits = out;                       // [B,S,O]
    float* out_ph     = out + (size_t)Mz*Oz;       // [B,S,H]
    float* out_wb     = out_ph + (size_t)Mz*Hz;    // [B,S,H]

    cudaFuncSetAttribute(readout_kernel, cudaFuncAttributeMaxDynamicSharedMemorySize, RD_SMEM);

    encoder_kernel<<<Mz/32, 256>>>(x, We, be);
    zero_kernel<<<1, 1>>>();
    rep_kernel<<<Sz, 256>>>(x);
    bperm_kernel<<<(Oz*Kz + 255)/256, 256>>>(Wr);
    bperm4_kernel<<<(Oz*512 + 255)/256, 256>>>(Wr);
    bperm6_kernel<<<(Oz*256 + 255)/256, 256>>>(Wr);
    w45_kernel<<<2, 256>>>(Wr);
    recur_kernel<<<Bz, 128>>>(omega, out_ph, out_wb);
    readout_kernel<<<dim3(Oz/256, Mz/128), 256, RD_SMEM>>>(out_ph, out_wb, br, out_logits);
}

// round 16
// speedup vs baseline: 1.2420x; 1.1813x over previous
#include <cuda_runtime.h>
#include <cuda_fp16.h>
#include <cstdint>

#define Bz 128
#define Sz 1024
#define Dz 64
#define Hz 128
#define Oz 512
#define Mz (Bz*Sz)   /* 131072 */
#define Kz 1024
#define PI_F 3.14159265358979f
#define TWO_PI_F 6.28318530717959f

// ---- static device scratch ----
__device__ float g_pt [(size_t)Mz*Hz];                  // encoder output, PRE-WRAPPED
__device__ __align__(16) __half g_Bp [(size_t)Oz*Kz];   // 8-plane weights (slow path)
__device__ __align__(16) __half g_Bp4[(size_t)Oz*512];  // 4 trig planes (fast path) [n][h*4+jf]
__device__ __align__(16) __half g_Bp6[(size_t)Oz*256];  // ph hi/lo planes [n][h*2+j] (both = w6)
__device__ float g_W45[2*Oz];                           // column sums of w4, w5
__device__ int   g_rep[Sz];
__device__ int   g_anyrep;

// ============================ helpers ============================
__device__ __forceinline__ uint32_t h2_to_u32(__half2 v){
    return *reinterpret_cast<uint32_t*>(&v);
}
__device__ __forceinline__ uint32_t smem_u32(const void* p){
    uint32_t a;
    asm("{ .reg .u64 t; cvta.to.shared.u64 t, %1; cvt.u32.u64 %0, t; }" : "=r"(a) : "l"(p));
    return a;
}
__device__ __forceinline__ uint32_t swz(uint32_t b){ return b ^ ((b >> 3) & 0x70); }

__device__ __forceinline__ void ldsm_x4(uint32_t* r, uint32_t addr){
    asm volatile("ldmatrix.sync.aligned.m8n8.x4.shared.b16 {%0,%1,%2,%3}, [%4];"
        : "=r"(r[0]), "=r"(r[1]), "=r"(r[2]), "=r"(r[3]) : "r"(addr));
}
__device__ __forceinline__ void mma16816(float* d, const uint32_t* a, const uint32_t* b){
    asm volatile("mma.sync.aligned.m16n8k16.row.col.f32.f16.f16.f32 "
        "{%0,%1,%2,%3}, {%4,%5,%6,%7}, {%8,%9}, {%0,%1,%2,%3};"
        : "+f"(d[0]), "+f"(d[1]), "+f"(d[2]), "+f"(d[3])
        : "r"(a[0]), "r"(a[1]), "r"(a[2]), "r"(a[3]), "r"(b[0]), "r"(b[1]));
}
__device__ __forceinline__ void cp_async16(uint32_t dst, const void* src){
    asm volatile("cp.async.cg.shared.global [%0], [%1], 16;" :: "r"(dst), "l"(src));
}
#define CP_COMMIT() asm volatile("cp.async.commit_group;" ::: "memory")
#define CP_WAIT0()  asm volatile("cp.async.wait_group 0;" ::: "memory")

// ---- fast sin/sincos with magic-number range reduction ----
__device__ __forceinline__ float wrap_pi(float x){
    float k = fmaf(x, 0.15915494309189535f, 12582912.0f);
    k -= 12582912.0f;
    float r = fmaf(k, -6.28125f, x);
    r = fmaf(k, -1.9353071795864769e-3f, r);
    return r;
}
__device__ __forceinline__ float fsin(float x){ return __sinf(wrap_pi(x)); }
__device__ __forceinline__ void fsincos(float x, float* s, float* c){ __sincosf(wrap_pi(x), s, c); }

// ============================ 1) encoder (stores wrapped pt) ============================
__global__ __launch_bounds__(256) void encoder_kernel(const float* __restrict__ x,
                                                      const float* __restrict__ We,
                                                      const float* __restrict__ be){
    __shared__ __align__(16) float WeT[Dz*Hz];
    __shared__ float xs[32*Dz];
    int t = threadIdx.x;
    int m0 = blockIdx.x * 32;
    for (int i = t; i < Dz*Hz; i += 256){ int h = i >> 6, k = i & 63; WeT[k*Hz + h] = We[i]; }
    for (int i = t; i < 32*Dz; i += 256) xs[i] = x[(size_t)m0*Dz + i];
    __syncthreads();
    int r = t >> 3, hg = t & 7;
    float acc[16];
    #pragma unroll
    for (int j = 0; j < 16; j++) acc[j] = 0.f;
    #pragma unroll 4
    for (int k = 0; k < Dz; k++){
        float xv = xs[r*Dz + k];
        const float4* wp = (const float4*)&WeT[k*Hz + hg*16];
        float4 w0 = wp[0], w1 = wp[1], w2 = wp[2], w3 = wp[3];
        acc[0]=fmaf(xv,w0.x,acc[0]);   acc[1]=fmaf(xv,w0.y,acc[1]);
        acc[2]=fmaf(xv,w0.z,acc[2]);   acc[3]=fmaf(xv,w0.w,acc[3]);
        acc[4]=fmaf(xv,w1.x,acc[4]);   acc[5]=fmaf(xv,w1.y,acc[5]);
        acc[6]=fmaf(xv,w1.z,acc[6]);   acc[7]=fmaf(xv,w1.w,acc[7]);
        acc[8]=fmaf(xv,w2.x,acc[8]);   acc[9]=fmaf(xv,w2.y,acc[9]);
        acc[10]=fmaf(xv,w2.z,acc[10]); acc[11]=fmaf(xv,w2.w,acc[11]);
        acc[12]=fmaf(xv,w3.x,acc[12]); acc[13]=fmaf(xv,w3.y,acc[13]);
        acc[14]=fmaf(xv,w3.z,acc[14]); acc[15]=fmaf(xv,w3.w,acc[15]);
    }
    int m = m0 + r;
    #pragma unroll
    for (int j = 0; j < 16; j++){
        int h = hg*16 + j;
        g_pt[(size_t)m*Hz + h] = wrap_pi(acc[j] + be[h]);
    }
}

// ============================ 2) repeat flags ============================
__global__ void zero_kernel(){ g_anyrep = 0; }

__global__ void rep_kernel(const float* __restrict__ x){
    int s = blockIdx.x;
    int ok;
    if (s > 0){
        ok = 1;
        for (int i = threadIdx.x; i < Bz*Dz; i += 256){
            int b = i >> 6, d = i & 63;
            size_t idx = ((size_t)b*Sz + s)*Dz + d;
            if (x[idx] != x[idx - Dz]) { ok = 0; break; }
        }
    } else ok = 0;
    ok = __syncthreads_and(ok);
    if (threadIdx.x == 0){
        g_rep[s] = ok;
        if (ok) atomicOr(&g_anyrep, 1);
    }
}

// ============================ 3) recurrence ============================
__global__ __launch_bounds__(128) void recur_kernel(const float* __restrict__ omega,
                                                    float* __restrict__ out_ph,
                                                    float* __restrict__ out_wb){
    __shared__ float tbl[Sz];
    __shared__ int   reps[Sz];
    __shared__ int   any8[Sz/8];
    int b = blockIdx.x, h = threadIdx.x;
    for (int i = h; i < Sz; i += 128){
        reps[i] = g_rep[i];
        tbl[i]  = 0.25f*fsin(0.015625f*(float)(i+1));
    }
    __syncthreads();
    for (int i = h; i < Sz/8; i += 128){
        int a = 0;
        #pragma unroll
        for (int j = 0; j < 8; j++) a |= reps[i*8 + j];
        any8[i] = a;
    }
    __syncthreads();

    float om = omega[h];
    float ph = 0.f, phw = 0.f, wb = 0.f;
    bool div = false;
    const float* ptp = g_pt + (size_t)b*Sz*Hz + h;
    float* php = out_ph + (size_t)b*Sz*Hz + h;
    float* wbp = out_wb + (size_t)b*Sz*Hz + h;

    for (int s0 = 0; s0 < Sz; s0 += 8){
        float pts[8];
        #pragma unroll
        for (int j = 0; j < 8; j++) pts[j] = ptp[(size_t)(s0 + j)*Hz];
        if (!div && !any8[s0 >> 3]){
            #pragma unroll
            for (int j = 0; j < 8; j++){
                int s = s0 + j;
                wb += 0.015625f;
                float c = om + tbl[s];
                float t = c - __sinf(pts[j] - phw);
                ph  += t;
                phw += t;
                float k = fmaf(phw, 0.15915494309189535f, 12582912.0f) - 12582912.0f;
                phw = fmaf(k, -6.28125f, phw);
                phw = fmaf(k, -1.9353071795864769e-3f, phw);
                php[(size_t)s*Hz] = ph;
                wbp[(size_t)s*Hz] = wb;
            }
        } else {
            #pragma unroll
            for (int j = 0; j < 8; j++){
                int s = s0 + j;
                wb += 0.015625f;
                float c = om + 0.25f*fsin(wb);
                float t = c - __sinf(pts[j] - phw);
                float phn  = ph + t;
                float phwn = phw + t;
                if (reps[s]) { wb += 0.25f*fsin(pts[j] - wb); div = true; }
                ph = phn; phw = phwn;
                float k = fmaf(phw, 0.15915494309189535f, 12582912.0f) - 12582912.0f;
                phw = fmaf(k, -6.28125f, phw);
                phw = fmaf(k, -1.9353071795864769e-3f, phw);
                php[(size_t)s*Hz] = ph;
                wbp[(size_t)s*Hz] = wb;
            }
        }
    }
}

// ============================ 4) weight prep ============================
__global__ void bperm_kernel(const float* __restrict__ Wr){
    int i = blockIdx.x*256 + threadIdx.x;
    if (i < Oz*Kz){
        int n = i >> 10, k = i & 1023;
        int h = k >> 3, jf = k & 7;
        if (jf > 6) jf = 6;
        g_Bp[i] = __float2half(Wr[n*(7*Hz) + jf*Hz + h]);
    }
}
__global__ void bperm4_kernel(const float* __restrict__ Wr){
    int i = blockIdx.x*256 + threadIdx.x;
    if (i < Oz*512){
        int n = i >> 9, k = i & 511;
        int h = k >> 2, jf = k & 3;
        g_Bp4[i] = __float2half(Wr[n*(7*Hz) + jf*Hz + h]);
    }
}
__global__ void bperm6_kernel(const float* __restrict__ Wr){
    int i = blockIdx.x*256 + threadIdx.x;
    if (i < Oz*256){
        int n = i >> 8, k = i & 255;
        int h = k >> 1;
        g_Bp6[i] = __float2half(Wr[n*(7*Hz) + 6*Hz + h]);
    }
}
__global__ void w45_kernel(const float* __restrict__ Wr){
    int n = blockIdx.x*256 + threadIdx.x;
    if (n < Oz){
        float s4 = 0.f, s5 = 0.f;
        for (int h = 0; h < Hz; h++){
            s4 += Wr[n*(7*Hz) + 4*Hz + h];
            s5 += Wr[n*(7*Hz) + 5*Hz + h];
        }
        g_W45[n] = s4; g_W45[Oz + n] = s5;
    }
}

// ============================ 5) fused readout GEMM ============================
// Fast (no repeats): 12 K-chunks of 64: c<8 trig planes (K=512), c>=8 ph hi/lo (K=256);
//                    wb features via exact rank-2 epilogue. Coalesced A-gen (R9 mapping).
// Slow (any repeat): R9 K=1024 path, verbatim.
// smem: A 2x16K @0 | B 2x32K @32768 | brs @98304 | w45 @100352
#define RD_SMEM 102400

__global__ __launch_bounds__(256)
void readout_kernel(const float* __restrict__ ph_in, const float* __restrict__ wb_in,
                    const float* __restrict__ br, float* __restrict__ out){
    extern __shared__ __align__(128) char smem[];
    int t = threadIdx.x, wid = t >> 5, lane = t & 31;
    int n0 = blockIdx.x * 256, m0 = blockIdx.y * 128;
    int wm = wid & 3, wn = wid >> 2;               // warp tile: 32m x 128n

    int a_row = wm*32 + (lane & 7) + ((lane >> 3) & 1)*8;
    int a_kh  = (lane >> 4)*8;
    int b_row = wn*128 + (lane & 7) + (lane >> 4)*8;
    int b_kh  = ((lane >> 3) & 1)*8;
    int lr = lane >> 2, lc = (lane & 3)*2;

    char* Asm = smem;
    char* Bsm = smem + 32768;
    float* brs  = (float*)(smem + 98304);
    float* w45s = (float*)(smem + 100352);

    uint32_t As_b = smem_u32(Asm), Bs_b = smem_u32(Bsm);

    __align__(16) float acc[2][16][4];
    #pragma unroll
    for (int mt = 0; mt < 2; mt++)
        #pragma unroll
        for (int nt = 0; nt < 16; nt++)
            #pragma unroll
            for (int v = 0; v < 4; v++) acc[mt][nt][v] = 0.f;

    for (int i = t; i < Oz; i += 256) brs[i] = br[i];

    if (!g_anyrep){
        // ======================= FAST PATH (12 chunks) =======================
        if (t < 256){
            w45s[t]       = g_W45[n0 + t];
            w45s[256 + t] = g_W45[Oz + n0 + t];
        }
        const uint4* b4 = (const uint4*)g_Bp4;
        const uint4* b6 = (const uint4*)g_Bp6;
        int bn = t >> 3, bk16 = t & 7;             // B: 256n rows x 8 x16B per chunk
        int gm = t >> 3, gq = t & 7;               // A-gen: 8 lanes share row -> coalesced

        // ---- prologue: chunk 0 (trig) ----
        {
            #pragma unroll
            for (int it = 0; it < 8; it++){
                int n = bn + it*32;
                cp_async16(Bs_b + swz((uint32_t)(n*128 + bk16*16)),
                           &b4[(size_t)(n0 + n)*64 + bk16]);
            }
            CP_COMMIT();
            #pragma unroll
            for (int it = 0; it < 4; it++){
                int m = gm + it*32;
                float2 p = *(const float2*)&ph_in[(size_t)(m0 + m)*Hz + gq*2];
                float s2a, c2a; fsincos(0.5f*p.x, &s2a, &c2a);
                float s2b, c2b; fsincos(0.5f*p.y, &s2b, &c2b);
                uint4 v;
                v.x = h2_to_u32(__floats2half2_rn(fmaf(2.f*c2a, c2a, -1.f), 2.f*s2a*c2a));
                v.y = h2_to_u32(__floats2half2_rn(c2a, s2a));
                v.z = h2_to_u32(__floats2half2_rn(fmaf(2.f*c2b, c2b, -1.f), 2.f*s2b*c2b));
                v.w = h2_to_u32(__floats2half2_rn(c2b, s2b));
                *(uint4*)(Asm + swz((uint32_t)(m*128 + gq*16))) = v;
            }
            CP_WAIT0();
            __syncthreads();
        }

        for (int c = 0; c < 12; c++){
            int cur = c & 1, nxt = cur ^ 1;
            if (c < 11){
                int cn = c + 1;
                #pragma unroll
                for (int it = 0; it < 8; it++){
                    int n = bn + it*32;
                    const void* src = (cn < 8)
                        ? (const void*)&b4[(size_t)(n0 + n)*64 + cn*8 + bk16]
                        : (const void*)&b6[(size_t)(n0 + n)*32 + (cn - 8)*8 + bk16];
                    cp_async16(Bs_b + (uint32_t)(nxt*32768) + swz((uint32_t)(n*128 + bk16*16)), src);
                }
                CP_COMMIT();
            }
            // ---- MMA on cur ----
            uint32_t Ab = As_b + (uint32_t)(cur*16384);
            uint32_t Bb = Bs_b + (uint32_t)(cur*32768);
            #pragma unroll
            for (int ks = 0; ks < 4; ks++){
                uint32_t af[2][4];
                #pragma unroll
                for (int mt = 0; mt < 2; mt++)
                    ldsm_x4(af[mt], Ab + swz((uint32_t)((a_row + mt*16)*128 + (ks*16 + a_kh)*2)));
                uint32_t bf[8][4];
                #pragma unroll
                for (int ntp = 0; ntp < 8; ntp++)
                    ldsm_x4(bf[ntp], Bb + swz((uint32_t)((b_row + ntp*16)*128 + (ks*16 + b_kh)*2)));
                #pragma unroll
                for (int mt = 0; mt < 2; mt++)
                    #pragma unroll
                    for (int nt = 0; nt < 16; nt++)
                        mma16816(acc[mt][nt], af[mt], &bf[nt >> 1][(nt & 1)*2]);
            }
            if (c < 11){
                int cn = c + 1;
                char* As = Asm + nxt*16384;
                if (cn < 8){
                    #pragma unroll
                    for (int it = 0; it < 4; it++){
                        int m = gm + it*32;
                        float2 p = *(const float2*)&ph_in[(size_t)(m0 + m)*Hz + cn*16 + gq*2];
                        float s2a, c2a; fsincos(0.5f*p.x, &s2a, &c2a);
                        float s2b, c2b; fsincos(0.5f*p.y, &s2b, &c2b);
                        uint4 v;
                        v.x = h2_to_u32(__floats2half2_rn(fmaf(2.f*c2a, c2a, -1.f), 2.f*s2a*c2a));
                        v.y = h2_to_u32(__floats2half2_rn(c2a, s2a));
                        v.z = h2_to_u32(__floats2half2_rn(fmaf(2.f*c2b, c2b, -1.f), 2.f*s2b*c2b));
                        v.w = h2_to_u32(__floats2half2_rn(c2b, s2b));
                        *(uint4*)(As + swz((uint32_t)(m*128 + gq*16))) = v;
                    }
                } else {
                    int pc = cn - 8;
                    #pragma unroll
                    for (int it = 0; it < 4; it++){
                        int m = gm + it*32;
                        float4 p = *(const float4*)&ph_in[(size_t)(m0 + m)*Hz + pc*32 + gq*4];
                        __half i0 = __float2half(p.x), l0 = __float2half(p.x - __half2float(i0));
                        __half i1 = __float2half(p.y), l1 = __float2half(p.y - __half2float(i1));
                        __half i2 = __float2half(p.z), l2 = __float2half(p.z - __half2float(i2));
                        __half i3 = __float2half(p.w), l3 = __float2half(p.w - __half2float(i3));
                        uint4 v;
                        v.x = h2_to_u32(__halves2half2(i0, l0));
                        v.y = h2_to_u32(__halves2half2(i1, l1));
                        v.z = h2_to_u32(__halves2half2(i2, l2));
                        v.w = h2_to_u32(__halves2half2(i3, l3));
                        *(uint4*)(As + swz((uint32_t)(m*128 + gq*16))) = v;
                    }
                }
                CP_WAIT0();
            }
            __syncthreads();
        }

        // ---- epilogue: wb rank-2 + bias ----
        float cw[4], sw[4];
        #pragma unroll
        for (int j = 0; j < 4; j++){
            int m = m0 + wm*32 + j*8 + lr;
            int s = m & (Sz - 1);
            float wbv = (float)(s + 1) * 0.015625f;
            fsincos(wbv, &sw[j], &cw[j]);
        }
        #pragma unroll
        for (int mt = 0; mt < 2; mt++){
            #pragma unroll
            for (int nt = 0; nt < 16; nt++){
                int ln = wn*128 + nt*8 + lc;
                int n  = n0 + ln;
                float w40 = w45s[ln],     w41 = w45s[ln+1];
                float w50 = w45s[256+ln], w51 = w45s[256+ln+1];
                int m = m0 + wm*32 + mt*16 + lr;
                float b0 = brs[n], b1 = brs[n+1];
                float r0 = acc[mt][nt][0] + cw[mt*2]*w40 + sw[mt*2]*w50 + b0;
                float r1 = acc[mt][nt][1] + cw[mt*2]*w41 + sw[mt*2]*w51 + b1;
                float r2 = acc[mt][nt][2] + cw[mt*2+1]*w40 + sw[mt*2+1]*w50 + b0;
                float r3 = acc[mt][nt][3] + cw[mt*2+1]*w41 + sw[mt*2+1]*w51 + b1;
                *(float2*)&out[(size_t)m*Oz + n]       = make_float2(r0, r1);
                *(float2*)&out[(size_t)(m + 8)*Oz + n] = make_float2(r2, r3);
            }
        }
    } else {
        // ======================= SLOW PATH (K=1024, R9 verbatim) =======================
        int gm = t >> 3, ghl = t & 7;
        const uint4* bsrc = (const uint4*)g_Bp;
        int bn = t >> 3, bk16 = t & 7;
        {
            #pragma unroll
            for (int it = 0; it < 8; it++){
                int n = bn + it*32;
                cp_async16(Bs_b + swz((uint32_t)(n*128 + bk16*16)),
                           &bsrc[(size_t)(n0 + n)*128 + bk16]);
            }
            CP_COMMIT();
            #pragma unroll
            for (int it = 0; it < 4; it++){
                int m = gm + it*32, h = ghl;
                float ph = ph_in[(size_t)(m0 + m)*Hz + h];
                float wb = wb_in[(size_t)(m0 + m)*Hz + h];
                float s2, c2; fsincos(0.5f*ph, &s2, &c2);
                float c1 = fmaf(2.f*c2, c2, -1.f);
                float s1 = 2.f*s2*c2;
                float s3, c3; fsincos(wb, &s3, &c3);
                __half hhi = __float2half(ph);
                __half hlo = __float2half(ph - __half2float(hhi));
                uint4 v;
                v.x = h2_to_u32(__floats2half2_rn(c1, s1));
                v.y = h2_to_u32(__floats2half2_rn(c2, s2));
                v.z = h2_to_u32(__floats2half2_rn(c3, s3));
                v.w = h2_to_u32(__halves2half2(hhi, hlo));
                *(uint4*)(Asm + swz((uint32_t)(m*128 + ghl*16))) = v;
            }
            CP_WAIT0();
            __syncthreads();
        }
        for (int c = 0; c < 16; c++){
            int cur = c & 1, nxt = cur ^ 1;
            float pr[4], wr[4];
            if (c < 15){
                #pragma unroll
                for (int it = 0; it < 8; it++){
                    int n = bn + it*32;
                    cp_async16(Bs_b + (uint32_t)(nxt*32768) + swz((uint32_t)(n*128 + bk16*16)),
                               &bsrc[(size_t)(n0 + n)*128 + (c+1)*8 + bk16]);
                }
                CP_COMMIT();
                int h = (c+1)*8 + ghl;
                #pragma unroll
                for (int it = 0; it < 4; it++){
                    int m = gm + it*32;
                    pr[it] = ph_in[(size_t)(m0 + m)*Hz + h];
                    wr[it] = wb_in[(size_t)(m0 + m)*Hz + h];
                }
            }
            uint32_t Ab = As_b + (uint32_t)(cur*16384);
            uint32_t Bb = Bs_b + (uint32_t)(cur*32768);
            #pragma unroll
            for (int ks = 0; ks < 4; ks++){
                uint32_t af[2][4];
                #pragma unroll
                for (int mt = 0; mt < 2; mt++)
                    ldsm_x4(af[mt], Ab + swz((uint32_t)((a_row + mt*16)*128 + (ks*16 + a_kh)*2)));
                uint32_t bf[8][4];
                #pragma unroll
                for (int ntp = 0; ntp < 8; ntp++)
                    ldsm_x4(bf[ntp], Bb + swz((uint32_t)((b_row + ntp*16)*128 + (ks*16 + b_kh)*2)));
                #pragma unroll
                for (int mt = 0; mt < 2; mt++)
                    #pragma unroll
                    for (int nt = 0; nt < 16; nt++)
                        mma16816(acc[mt][nt], af[mt], &bf[nt >> 1][(nt & 1)*2]);
            }
            if (c < 15){
                #pragma unroll
                for (int it = 0; it < 4; it++){
                    int m = gm + it*32;
                    float ph = pr[it], wb = wr[it];
                    float s2, c2; fsincos(0.5f*ph, &s2, &c2);
                    float c1 = fmaf(2.f*c2, c2, -1.f);
                    float s1 = 2.f*s2*c2;
                    float s3, c3; fsincos(wb, &s3, &c3);
                    __half hhi = __float2half(ph);
                    __half hlo = __float2half(ph - __half2float(hhi));
                    uint4 v;
                    v.x = h2_to_u32(__floats2half2_rn(c1, s1));
                    v.y = h2_to_u32(__floats2half2_rn(c2, s2));
                    v.z = h2_to_u32(__floats2half2_rn(c3, s3));
                    v.w = h2_to_u32(__halves2half2(hhi, hlo));
                    *(uint4*)(Asm + nxt*16384 + swz((uint32_t)(m*128 + ghl*16))) = v;
                }
                CP_WAIT0();
            }
            __syncthreads();
        }
        #pragma unroll
        for (int mt = 0; mt < 2; mt++){
            #pragma unroll
            for (int nt = 0; nt < 16; nt++){
                int m = m0 + wm*32 + mt*16 + lr;
                int n = n0 + wn*128 + nt*8 + lc;
                float b0 = brs[n], b1 = brs[n + 1];
                *(float2*)&out[(size_t)m*Oz + n]       = make_float2(acc[mt][nt][0] + b0, acc[mt][nt][1] + b1);
                *(float2*)&out[(size_t)(m + 8)*Oz + n] = make_float2(acc[mt][nt][2] + b0, acc[mt][nt][3] + b1);
            }
        }
    }
}

// ============================ launch ============================
extern "C" void kernel_launch(void* const* d_in, const int* in_sizes, int n_in,
                              void* d_out, int out_size){
    const float* x     = (const float*)d_in[0];
    const float* We    = (const float*)d_in[1];
    const float* be    = (const float*)d_in[2];
    const float* omega = (const float*)d_in[3];
    const float* Wr    = (const float*)d_in[4];
    const float* br    = (const float*)d_in[5];
    float* out        = (float*)d_out;
    float* out_logits = out;                       // [B,S,O]
    float* out_ph     = out + (size_t)Mz*Oz;       // [B,S,H]
    float* out_wb     = out_ph + (size_t)Mz*Hz;    // [B,S,H]

    cudaFuncSetAttribute(readout_kernel, cudaFuncAttributeMaxDynamicSharedMemorySize, RD_SMEM);

    encoder_kernel<<<Mz/32, 256>>>(x, We, be);
    zero_kernel<<<1, 1>>>();
    rep_kernel<<<Sz, 256>>>(x);
    bperm_kernel<<<(Oz*Kz + 255)/256, 256>>>(Wr);
    bperm4_kernel<<<(Oz*512 + 255)/256, 256>>>(Wr);
    bperm6_kernel<<<(Oz*256 + 255)/256, 256>>>(Wr);
    w45_kernel<<<2, 256>>>(Wr);
    recur_kernel<<<Bz, 128>>>(omega, out_ph, out_wb);
    readout_kernel<<<dim3(Oz/256, Mz/128), 256, RD_SMEM>>>(out_ph, out_wb, br, out_logits);
}